// round 14
// baseline (speedup 1.0000x reference)
#include <cuda_runtime.h>
#include <cuda_fp16.h>

// PolyConv: h = sum_k theta_k * L_sym^k x. N=100000, E=1600000, F=64.
//
// R9 post-mortem: props below LTS cap (~3300 B/cyc) -> latency/MLP bound.
// R10-R14: (1) de-fuse h (separate s1..s4 buffers + one final elementwise
// combine) removing the 51MB/prop h RMW; (2) unroll 8 -> 16 outstanding
// loads per warp. Buffer selection via in-kernel switch (no host-side
// symbol-address calls in the capture path).

#define NN 100000
#define EE 1600000
#define FF 64
#define SCAN_BLK 1024
#define NBLKS ((NN + SCAN_BLK - 1) / SCAN_BLK)   // 98

__device__ int   g_is_i64;
__device__ int   g_src[EE];
__device__ int   g_dst[EE];
__device__ int   g_deg[NN];
__device__ int   g_rowptr[NN + 1];
__device__ int   g_cursor[NN];
__device__ int   g_blocksum[NBLKS];
__device__ float g_dis[NN];    // d^{-1/2}
__device__ float g_dis2[NN];   // 1/d
__device__ float g_dinv[NN];   // d^{1/2}
__device__ int   g_col[EE];    // src ids grouped by dst
// fp16 scaled-space iterates s_k = D^{-1/2} feat_k  (half2 = 2 features)
__device__ __align__(256) __half2 g_s0[(size_t)NN * 32];
__device__ __align__(256) __half2 g_s1[(size_t)NN * 32];
__device__ __align__(256) __half2 g_s2[(size_t)NN * 32];
__device__ __align__(256) __half2 g_s3[(size_t)NN * 32];
__device__ __align__(256) __half2 g_s4[(size_t)NN * 32];

__device__ __forceinline__ __half2* sel_buf(int k) {
    switch (k) {
        case 0: return g_s0;
        case 1: return g_s1;
        case 2: return g_s2;
        case 3: return g_s3;
        default: return g_s4;
    }
}

// Probe dtype: true-int64 values < 2^32 have all-zero high words.
__global__ void detect_kernel(const unsigned int* __restrict__ w) {
    __shared__ unsigned int s_acc[256];
    unsigned int acc = 0;
    for (int i = threadIdx.x; i < 4096; i += 256) acc |= w[2 * i + 1];
    s_acc[threadIdx.x] = acc;
    __syncthreads();
    for (int off = 128; off > 0; off >>= 1) {
        if (threadIdx.x < off) s_acc[threadIdx.x] |= s_acc[threadIdx.x + off];
        __syncthreads();
    }
    if (threadIdx.x == 0) g_is_i64 = (s_acc[0] == 0) ? 1 : 0;
}

__global__ void zero_deg_kernel() {
    int i = blockIdx.x * blockDim.x + threadIdx.x;
    if (i < NN) g_deg[i] = 0;
}

// Normalize edges to clamped int32 AND count in-degrees in one pass.
__global__ void convert_count_kernel(const void* __restrict__ ei) {
    int e = blockIdx.x * blockDim.x + threadIdx.x;
    if (e >= EE) return;
    int s, d;
    if (g_is_i64) {
        const long long* p = (const long long*)ei;
        s = (int)p[e];
        d = (int)p[e + EE];
    } else {
        const int* p = (const int*)ei;
        s = p[e];
        d = p[e + EE];
    }
    s = min(max(s, 0), NN - 1);
    d = min(max(d, 0), NN - 1);
    g_src[e] = s;
    g_dst[e] = d;
    atomicAdd(&g_deg[d], 1);
}

// --- parallel scan, 3 passes ---
__global__ void __launch_bounds__(SCAN_BLK) scanA_kernel() {
    __shared__ int sh[SCAN_BLK];
    int tid = threadIdx.x;
    int i = blockIdx.x * SCAN_BLK + tid;
    int v = (i < NN) ? g_deg[i] : 0;
    sh[tid] = v;
    __syncthreads();
    for (int off = 1; off < SCAN_BLK; off <<= 1) {
        int t = (tid >= off) ? sh[tid - off] : 0;
        __syncthreads();
        sh[tid] += t;
        __syncthreads();
    }
    if (i < NN) g_rowptr[i] = sh[tid] - v;
    if (tid == SCAN_BLK - 1) g_blocksum[blockIdx.x] = sh[tid];
}

__global__ void scanB_kernel() {
    __shared__ int sh[128];
    int tid = threadIdx.x;
    int v = (tid < NBLKS) ? g_blocksum[tid] : 0;
    sh[tid] = v;
    __syncthreads();
    for (int off = 1; off < 128; off <<= 1) {
        int t = (tid >= off) ? sh[tid - off] : 0;
        __syncthreads();
        sh[tid] += t;
        __syncthreads();
    }
    if (tid < NBLKS) g_blocksum[tid] = sh[tid] - v;
    if (tid == 0) g_rowptr[NN] = EE;
}

__global__ void __launch_bounds__(SCAN_BLK) scanC_kernel() {
    int i = blockIdx.x * SCAN_BLK + threadIdx.x;
    if (i >= NN) return;
    int r = g_rowptr[i] + g_blocksum[blockIdx.x];
    g_rowptr[i] = r;
    g_cursor[i] = r;
    int d = g_deg[i]; if (d < 1) d = 1;
    float df = (float)d;
    g_dis[i]  = rsqrtf(df);
    g_dis2[i] = 1.0f / df;
    g_dinv[i] = sqrtf(df);
}

// s0 = fp16(D^{-1/2} x)
__global__ void prescale_kernel(const float2* __restrict__ x2) {
    int idx = blockIdx.x * blockDim.x + threadIdx.x;   // NN*32 half2 elems
    if (idx >= NN * 32) return;
    int node = idx >> 5;
    float dis = g_dis[node];
    float2 v = x2[idx];
    g_s0[idx] = __floats2half2_rn(v.x * dis, v.y * dis);
}

__global__ void fill_kernel() {
    int e = blockIdx.x * blockDim.x + threadIdx.x;
    if (e < EE) {
        int pos = atomicAdd(&g_cursor[g_dst[e]], 1);
        g_col[pos] = g_src[e];
    }
}

// One warp per dst node; lane owns features [2*lane, 2*lane+1] as half2.
// agg = sum_{src} s[src];  s_out[i] = s_in[i] - (1/d_i) * agg.
// Pure gather -> write (h handled by final combine kernel). Unroll 8.
__global__ void __launch_bounds__(256) prop_kernel(int k)
{
    int gw = (blockIdx.x * blockDim.x + threadIdx.x) >> 5;
    if (gw >= NN) return;
    int lane = threadIdx.x & 31;

    const __half2* __restrict__ fin = sel_buf(k - 1);
    __half2* __restrict__ fout      = sel_buf(k);

    int start = __ldg(&g_rowptr[gw]);
    int end   = __ldg(&g_rowptr[gw + 1]);

    float ax0 = 0.f, ay0 = 0.f, ax1 = 0.f, ay1 = 0.f;
    int j = start;
    // 8-deep: 8 col + 8 feat loads in flight
    for (; j + 8 <= end; j += 8) {
        int s0 = __ldg(&g_col[j + 0]);
        int s1 = __ldg(&g_col[j + 1]);
        int s2 = __ldg(&g_col[j + 2]);
        int s3 = __ldg(&g_col[j + 3]);
        int s4 = __ldg(&g_col[j + 4]);
        int s5 = __ldg(&g_col[j + 5]);
        int s6 = __ldg(&g_col[j + 6]);
        int s7 = __ldg(&g_col[j + 7]);
        float2 f0 = __half22float2(fin[(size_t)s0 * 32 + lane]);
        float2 f1 = __half22float2(fin[(size_t)s1 * 32 + lane]);
        float2 f2 = __half22float2(fin[(size_t)s2 * 32 + lane]);
        float2 f3 = __half22float2(fin[(size_t)s3 * 32 + lane]);
        float2 f4 = __half22float2(fin[(size_t)s4 * 32 + lane]);
        float2 f5 = __half22float2(fin[(size_t)s5 * 32 + lane]);
        float2 f6 = __half22float2(fin[(size_t)s6 * 32 + lane]);
        float2 f7 = __half22float2(fin[(size_t)s7 * 32 + lane]);
        ax0 += f0.x; ay0 += f0.y;  ax1 += f1.x; ay1 += f1.y;
        ax0 += f2.x; ay0 += f2.y;  ax1 += f3.x; ay1 += f3.y;
        ax0 += f4.x; ay0 += f4.y;  ax1 += f5.x; ay1 += f5.y;
        ax0 += f6.x; ay0 += f6.y;  ax1 += f7.x; ay1 += f7.y;
    }
    for (; j + 4 <= end; j += 4) {
        int s0 = __ldg(&g_col[j + 0]);
        int s1 = __ldg(&g_col[j + 1]);
        int s2 = __ldg(&g_col[j + 2]);
        int s3 = __ldg(&g_col[j + 3]);
        float2 f0 = __half22float2(fin[(size_t)s0 * 32 + lane]);
        float2 f1 = __half22float2(fin[(size_t)s1 * 32 + lane]);
        float2 f2 = __half22float2(fin[(size_t)s2 * 32 + lane]);
        float2 f3 = __half22float2(fin[(size_t)s3 * 32 + lane]);
        ax0 += f0.x; ay0 += f0.y;  ax1 += f1.x; ay1 += f1.y;
        ax0 += f2.x; ay0 += f2.y;  ax1 += f3.x; ay1 += f3.y;
    }
    for (; j < end; j++) {
        int s = __ldg(&g_col[j]);
        float2 f = __half22float2(fin[(size_t)s * 32 + lane]);
        ax0 += f.x; ay0 += f.y;
    }
    float ax = ax0 + ax1;
    float ay = ay0 + ay1;

    float d2 = __ldg(&g_dis2[gw]);
    size_t self = (size_t)gw * 32 + lane;
    float2 si = __half22float2(fin[self]);
    fout[self] = __floats2half2_rn(si.x - d2 * ax, si.y - d2 * ay);
}

// h = theta0*x + sum_k theta_k * sqrt(d) * s_k   (elementwise, streaming)
__global__ void combine_kernel(const float2* __restrict__ x2,
                               float2* __restrict__ h2)
{
    int idx = blockIdx.x * blockDim.x + threadIdx.x;   // NN*32 half2 slots
    if (idx >= NN * 32) return;
    int node = idx >> 5;
    float dv = g_dinv[node];
    float2 xv = x2[idx];
    float2 v1 = __half22float2(g_s1[idx]);
    float2 v2 = __half22float2(g_s2[idx]);
    float2 v3 = __half22float2(g_s3[idx]);
    float2 v4 = __half22float2(g_s4[idx]);
    float hx = 0.6f * xv.x + dv * (-0.4f * v1.x + 0.3f * v2.x - 0.2f * v3.x + 0.1f * v4.x);
    float hy = 0.6f * xv.y + dv * (-0.4f * v1.y + 0.3f * v2.y - 0.2f * v3.y + 0.1f * v4.y);
    h2[idx] = make_float2(hx, hy);
}

extern "C" void kernel_launch(void* const* d_in, const int* in_sizes, int n_in,
                              void* d_out, int out_size)
{
    const float* x = (const float*)d_in[0];
    const void* ei = d_in[1];
    for (int i = 0; i < n_in; i++) {
        if (in_sizes[i] == 2 * EE) ei = d_in[i];
        else if (in_sizes[i] == NN * FF) x = (const float*)d_in[i];
    }
    float2* h2 = (float2*)d_out;
    const float2* x2 = (const float2*)x;

    // --- dtype probe, normalize edges + count degrees ---
    detect_kernel<<<1, 256>>>((const unsigned int*)ei);
    zero_deg_kernel<<<(NN + 255) / 256, 256>>>();
    convert_count_kernel<<<(EE + 255) / 256, 256>>>(ei);

    // --- CSR build + prescale ---
    scanA_kernel<<<NBLKS, SCAN_BLK>>>();
    scanB_kernel<<<1, 128>>>();
    scanC_kernel<<<NBLKS, SCAN_BLK>>>();
    prescale_kernel<<<(NN * 32 + 255) / 256, 256>>>(x2);
    fill_kernel<<<(EE + 255) / 256, 256>>>();

    // --- 4 pure propagation rounds + one combine ---
    int blocks = ((size_t)NN * 32 + 255) / 256;
    prop_kernel<<<blocks, 256>>>(1);   // s0 -> s1
    prop_kernel<<<blocks, 256>>>(2);   // s1 -> s2
    prop_kernel<<<blocks, 256>>>(3);   // s2 -> s3
    prop_kernel<<<blocks, 256>>>(4);   // s3 -> s4
    combine_kernel<<<(NN * 32 + 255) / 256, 256>>>(x2, h2);
}